// round 6
// baseline (speedup 1.0000x reference)
#include <cuda_runtime.h>
#include <cuda_fp16.h>
#include <cstdint>

// Problem constants
#define B_  8
#define T_  256
#define U_  64
#define D_  512
#define V_  1024

// Tiling
#define BM 128            // rows per m-tile (2 t-values x 64 u)
#define BN 128            // cols per CTA
#define KC 32             // k-chunk (2 x K=16 MMA steps)
#define NCHUNK 16         // D_/KC
#define TILES 8           // m-tiles per CTA

#define BS_STRIDE 520     // halves per B row (512 + 8 pad) -> 1040B, conflict-free ldmatrix
#define AS_STRIDE 40      // halves per A row (32 + 8 pad)  -> 80B,  conflict-free ldmatrix
#define AS_TILE   (BM * AS_STRIDE)      // 5120 halves per stage

// smem (halves): Bs [128][520] = 66560 ; As 2 stages x 5120 = 10240
#define OFF_AS    66560
#define SMEM_HALVES (66560 + 2 * AS_TILE)          // 76800 halves = 153600 B

__device__ __align__(16) __half g_W16[V_ * D_];

__global__ void convert_w_kernel(const float* __restrict__ W) {
    int i = (blockIdx.x * blockDim.x + threadIdx.x) * 4;
    float4 w = *(const float4*)(W + i);
    union { __half2 h[2]; uint2 u; } pack;
    pack.h[0] = __floats2half2_rn(w.x, w.y);
    pack.h[1] = __floats2half2_rn(w.z, w.w);
    *(uint2*)(g_W16 + i) = pack.u;
}

__global__ void write_lengths_kernel(const int* __restrict__ slen,
                                     const int* __restrict__ tlen,
                                     float* __restrict__ out_tail) {
    int i = threadIdx.x;
    if (i < B_)          out_tail[i] = (float)slen[i];
    else if (i < 2 * B_) out_tail[i] = (float)tlen[i - B_];
}

// Load next chunk's A operands into registers (2 threads per row, 16 k each).
__device__ __forceinline__ void load_next(const float* __restrict__ src,
                                          const float* __restrict__ tgt,
                                          int m_base, int c, int tid,
                                          float4 rs[4], float4 rt[4]) {
    int r = tid >> 1, h = tid & 1;
    int b = m_base >> 14;
    int t_idx = ((m_base & 16383) >> 6) + (r >> 6);
    const float4* sp = (const float4*)(src + (size_t)(b * T_ + t_idx) * D_ + c * KC + h * 16);
    const float4* tp = (const float4*)(tgt + (size_t)(b * U_ + (r & 63)) * D_ + c * KC + h * 16);
    #pragma unroll
    for (int j = 0; j < 4; ++j) { rs[j] = sp[j]; rt[j] = tp[j]; }
}

// relu(src+tgt) -> fp16, store 16 halves into stage s.
__device__ __forceinline__ void store_next(__half* __restrict__ As, int s, int tid,
                                           const float4 rs[4], const float4 rt[4]) {
    int r = tid >> 1, h = tid & 1;
    __half* dst = As + s * AS_TILE + r * AS_STRIDE + h * 16;
    #pragma unroll
    for (int j = 0; j < 2; ++j) {
        float4 a0 = rs[2 * j],     b0 = rt[2 * j];
        float4 a1 = rs[2 * j + 1], b1 = rt[2 * j + 1];
        union { __half2 h2[4]; uint4 v; } pk;
        pk.h2[0] = __floats2half2_rn(fmaxf(a0.x + b0.x, 0.f), fmaxf(a0.y + b0.y, 0.f));
        pk.h2[1] = __floats2half2_rn(fmaxf(a0.z + b0.z, 0.f), fmaxf(a0.w + b0.w, 0.f));
        pk.h2[2] = __floats2half2_rn(fmaxf(a1.x + b1.x, 0.f), fmaxf(a1.y + b1.y, 0.f));
        pk.h2[3] = __floats2half2_rn(fmaxf(a1.z + b1.z, 0.f), fmaxf(a1.w + b1.w, 0.f));
        *(uint4*)(dst + j * 8) = pk.v;
    }
}

__device__ __forceinline__ void compute_chunk(const __half* __restrict__ As_s,
                                              const __half* __restrict__ Bs, int c,
                                              int warp_row, int warp_col, int lane,
                                              float acc[4][4][4]) {
    #pragma unroll
    for (int kk = 0; kk < KC; kk += 16) {
        uint32_t afr[4][4], bfr[4][2];
        #pragma unroll
        for (int mt = 0; mt < 4; ++mt) {
            int row = warp_row * 64 + mt * 16 + (lane & 15);
            int col = kk + ((lane >> 4) << 3);
            uint32_t addr = (uint32_t)__cvta_generic_to_shared(As_s + row * AS_STRIDE + col);
            asm volatile("ldmatrix.sync.aligned.m8n8.x4.shared.b16 {%0,%1,%2,%3}, [%4];"
                         : "=r"(afr[mt][0]), "=r"(afr[mt][1]), "=r"(afr[mt][2]), "=r"(afr[mt][3])
                         : "r"(addr));
        }
        #pragma unroll
        for (int nt = 0; nt < 4; ++nt) {
            int row = warp_col * 32 + nt * 8 + (lane & 7);
            int col = c * KC + kk + (((lane >> 3) & 1) << 3);
            uint32_t addr = (uint32_t)__cvta_generic_to_shared(Bs + row * BS_STRIDE + col);
            asm volatile("ldmatrix.sync.aligned.m8n8.x2.shared.b16 {%0,%1}, [%2];"
                         : "=r"(bfr[nt][0]), "=r"(bfr[nt][1])
                         : "r"(addr));
        }
        #pragma unroll
        for (int mt = 0; mt < 4; ++mt)
            #pragma unroll
            for (int nt = 0; nt < 4; ++nt) {
                asm volatile(
                    "mma.sync.aligned.m16n8k16.row.col.f32.f16.f16.f32 "
                    "{%0,%1,%2,%3}, {%4,%5,%6,%7}, {%8,%9}, {%0,%1,%2,%3};"
                    : "+f"(acc[mt][nt][0]), "+f"(acc[mt][nt][1]),
                      "+f"(acc[mt][nt][2]), "+f"(acc[mt][nt][3])
                    : "r"(afr[mt][0]), "r"(afr[mt][1]), "r"(afr[mt][2]), "r"(afr[mt][3]),
                      "r"(bfr[nt][0]), "r"(bfr[nt][1]));
            }
    }
}

__global__ void __launch_bounds__(256, 1)
joiner_gemm_kernel(const float* __restrict__ src, const float* __restrict__ tgt,
                   const float* __restrict__ bias, float* __restrict__ out)
{
    extern __shared__ __half sm[];
    __half* Bs = sm;
    __half* As = sm + OFF_AS;

    const int tid  = threadIdx.x;
    const int lane = tid & 31;
    const int warp = tid >> 5;
    const int warp_row = warp >> 2;
    const int warp_col = warp & 3;
    const int v0 = blockIdx.x * BN;

    // ---- B prologue: full-K weight tile resident, 128 rows x 512 halves ----
    #pragma unroll
    for (int it = 0; it < 32; ++it) {
        int G = tid + it * 256;        // 16B group id, 0..8191
        int n = G >> 6;
        int g = G & 63;
        uint4 w = *(const uint4*)(g_W16 + (size_t)(v0 + n) * D_ + g * 8);
        *(uint4*)(Bs + n * BS_STRIDE + g * 8) = w;
    }

    for (int tau = 0; tau < TILES; ++tau) {
        const int m_base = (blockIdx.y * TILES + tau) * BM;

        float acc[4][4][4];
        #pragma unroll
        for (int i = 0; i < 4; ++i)
            #pragma unroll
            for (int j = 0; j < 4; ++j)
                #pragma unroll
                for (int k = 0; k < 4; ++k) acc[i][j][k] = 0.f;

        // fill chunk 0 into stage 0
        {
            float4 rs[4], rt[4];
            load_next(src, tgt, m_base, 0, tid, rs, rt);
            store_next(As, 0, tid, rs, rt);
        }
        __syncthreads();

        for (int c = 0; c < NCHUNK; ++c) {
            const int s = c & 1;
            float4 rs[4], rt[4];
            if (c < NCHUNK - 1) load_next(src, tgt, m_base, c + 1, tid, rs, rt);
            compute_chunk(As + s * AS_TILE, Bs, c, warp_row, warp_col, lane, acc);
            if (c < NCHUNK - 1) store_next(As, s ^ 1, tid, rs, rt);
            __syncthreads();
        }

        // ---- epilogue: bias + fp32 store ----
        #pragma unroll
        for (int nt = 0; nt < 4; ++nt) {
            int col = v0 + warp_col * 32 + nt * 8 + ((lane & 3) << 1);
            float2 bv = *(const float2*)(bias + col);
            #pragma unroll
            for (int mt = 0; mt < 4; ++mt) {
                int row = m_base + warp_row * 64 + mt * 16 + (lane >> 2);
                float2 r0 = make_float2(acc[mt][nt][0] + bv.x, acc[mt][nt][1] + bv.y);
                float2 r1 = make_float2(acc[mt][nt][2] + bv.x, acc[mt][nt][3] + bv.y);
                *(float2*)(out + (size_t)row * V_ + col)       = r0;
                *(float2*)(out + (size_t)(row + 8) * V_ + col) = r1;
            }
        }
        // no sync needed: next iteration's first smem write (stage 0) was last
        // read two chunks before the final sync of this tile's chunk loop
    }
}

extern "C" void kernel_launch(void* const* d_in, const int* in_sizes, int n_in,
                              void* d_out, int out_size) {
    const float* src  = (const float*)d_in[0];
    const int*   slen = (const int*)  d_in[1];
    const float* tgt  = (const float*)d_in[2];
    const int*   tlen = (const int*)  d_in[3];
    const float* W    = (const float*)d_in[4];
    const float* bias = (const float*)d_in[5];
    float* out = (float*)d_out;

    convert_w_kernel<<<512, 256>>>(W);

    static bool attr_set = false;
    if (!attr_set) {
        cudaFuncSetAttribute(joiner_gemm_kernel,
                             cudaFuncAttributeMaxDynamicSharedMemorySize,
                             SMEM_HALVES * 2);
        attr_set = true;
    }
    dim3 grid(V_ / BN, (B_ * T_ * U_) / (BM * TILES));   // (8, 128)
    joiner_gemm_kernel<<<grid, 256, SMEM_HALVES * 2>>>(src, tgt, bias, out);

    const long long N_OUT = (long long)B_ * T_ * U_ * V_;
    if ((long long)out_size >= N_OUT + 2 * B_) {
        write_lengths_kernel<<<1, 32>>>(slen, tlen, out + N_OUT);
    }
}

// round 8
// speedup vs baseline: 1.2115x; 1.2115x over previous
#include <cuda_runtime.h>
#include <cuda_fp16.h>
#include <cstdint>

// Problem constants
#define B_  8
#define T_  256
#define U_  64
#define D_  512
#define V_  1024

// Tiling
#define BM 128            // rows per CTA tile
#define BN 128            // cols per CTA tile
#define KC 32             // k-chunk (2 x K=16 MMA steps)
#define NCHUNK 16         // D_/KC
#define ST 40             // smem row stride in halves (32 + 8 pad) -> 80B, conflict-free
#define TILE_H (BM * ST)  // 5120 halves per stage

__device__ __align__(16) __half g_W16[V_ * D_];

__global__ void convert_w_kernel(const float* __restrict__ W) {
    int i = (blockIdx.x * blockDim.x + threadIdx.x) * 4;
    float4 w = *(const float4*)(W + i);
    union { __half2 h[2]; uint2 u; } pack;
    pack.h[0] = __floats2half2_rn(w.x, w.y);
    pack.h[1] = __floats2half2_rn(w.z, w.w);
    *(uint2*)(g_W16 + i) = pack.u;
}

__global__ void write_lengths_kernel(const int* __restrict__ slen,
                                     const int* __restrict__ tlen,
                                     float* __restrict__ out_tail) {
    int i = threadIdx.x;
    if (i < B_)          out_tail[i] = (float)slen[i];
    else if (i < 2 * B_) out_tail[i] = (float)tlen[i - B_];
}

__device__ __forceinline__ void cp_async16(void* smem_dst, const void* gsrc) {
    uint32_t d = (uint32_t)__cvta_generic_to_shared(smem_dst);
    asm volatile("cp.async.ca.shared.global [%0], [%1], 16;" :: "r"(d), "l"(gsrc));
}
#define CP_COMMIT() asm volatile("cp.async.commit_group;" ::: "memory")
#define CP_WAIT0()  asm volatile("cp.async.wait_group 0;" ::: "memory")

// cp.async chunk c of B into stage buffer (64B per row = 4x16B; 2 ops/thread).
__device__ __forceinline__ void cp_B(__half* Bs_s, int v0, int c, int tid) {
    #pragma unroll
    for (int it = 0; it < 2; ++it) {
        int G = tid + it * 256;       // 0..511 : 16B group id
        int n = G >> 2;               // B row 0..127
        int g = G & 3;                // 16B group within row
        cp_async16(Bs_s + n * ST + g * 8,
                   g_W16 + (size_t)(v0 + n) * D_ + c * KC + g * 8);
    }
}

// Load chunk c's A operands into regs (2 threads per row, 16 k-values each).
__device__ __forceinline__ void load_A(const float* __restrict__ src,
                                       const float* __restrict__ tgt,
                                       int m_base, int c, int tid,
                                       float4 rs[4], float4 rt[4]) {
    int r = tid >> 1, h = tid & 1;
    int b = m_base >> 14;
    int t_idx = ((m_base & 16383) >> 6) + (r >> 6);
    const float4* sp = (const float4*)(src + (size_t)(b * T_ + t_idx) * D_ + c * KC + h * 16);
    const float4* tp = (const float4*)(tgt + (size_t)(b * U_ + (r & 63)) * D_ + c * KC + h * 16);
    #pragma unroll
    for (int j = 0; j < 4; ++j) { rs[j] = sp[j]; rt[j] = tp[j]; }
}

// relu(src+tgt) -> fp16, store 16 halves.
__device__ __forceinline__ void store_A(__half* __restrict__ As_s, int tid,
                                        const float4 rs[4], const float4 rt[4]) {
    int r = tid >> 1, h = tid & 1;
    __half* dst = As_s + r * ST + h * 16;
    #pragma unroll
    for (int j = 0; j < 2; ++j) {
        float4 a0 = rs[2 * j],     b0 = rt[2 * j];
        float4 a1 = rs[2 * j + 1], b1 = rt[2 * j + 1];
        union { __half2 h2[4]; uint4 v; } pk;
        pk.h2[0] = __floats2half2_rn(fmaxf(a0.x + b0.x, 0.f), fmaxf(a0.y + b0.y, 0.f));
        pk.h2[1] = __floats2half2_rn(fmaxf(a0.z + b0.z, 0.f), fmaxf(a0.w + b0.w, 0.f));
        pk.h2[2] = __floats2half2_rn(fmaxf(a1.x + b1.x, 0.f), fmaxf(a1.y + b1.y, 0.f));
        pk.h2[3] = __floats2half2_rn(fmaxf(a1.z + b1.z, 0.f), fmaxf(a1.w + b1.w, 0.f));
        *(uint4*)(dst + j * 8) = pk.v;
    }
}

__device__ __forceinline__ void compute_chunk(const __half* __restrict__ As_s,
                                              const __half* __restrict__ Bs_s,
                                              int warp_row, int warp_col, int lane,
                                              float acc[4][4][4]) {
    #pragma unroll
    for (int kk = 0; kk < KC; kk += 16) {
        uint32_t afr[4][4], bfr[4][2];
        #pragma unroll
        for (int mt = 0; mt < 4; ++mt) {
            int row = warp_row * 64 + mt * 16 + (lane & 15);
            int col = kk + ((lane >> 4) << 3);
            uint32_t addr = (uint32_t)__cvta_generic_to_shared(As_s + row * ST + col);
            asm volatile("ldmatrix.sync.aligned.m8n8.x4.shared.b16 {%0,%1,%2,%3}, [%4];"
                         : "=r"(afr[mt][0]), "=r"(afr[mt][1]), "=r"(afr[mt][2]), "=r"(afr[mt][3])
                         : "r"(addr));
        }
        #pragma unroll
        for (int nt = 0; nt < 4; ++nt) {
            int row = warp_col * 32 + nt * 8 + (lane & 7);
            int col = kk + (((lane >> 3) & 1) << 3);
            uint32_t addr = (uint32_t)__cvta_generic_to_shared(Bs_s + row * ST + col);
            asm volatile("ldmatrix.sync.aligned.m8n8.x2.shared.b16 {%0,%1}, [%2];"
                         : "=r"(bfr[nt][0]), "=r"(bfr[nt][1])
                         : "r"(addr));
        }
        #pragma unroll
        for (int mt = 0; mt < 4; ++mt)
            #pragma unroll
            for (int nt = 0; nt < 4; ++nt) {
                asm volatile(
                    "mma.sync.aligned.m16n8k16.row.col.f32.f16.f16.f32 "
                    "{%0,%1,%2,%3}, {%4,%5,%6,%7}, {%8,%9}, {%0,%1,%2,%3};"
                    : "+f"(acc[mt][nt][0]), "+f"(acc[mt][nt][1]),
                      "+f"(acc[mt][nt][2]), "+f"(acc[mt][nt][3])
                    : "r"(afr[mt][0]), "r"(afr[mt][1]), "r"(afr[mt][2]), "r"(afr[mt][3]),
                      "r"(bfr[nt][0]), "r"(bfr[nt][1]));
            }
    }
}

__global__ void __launch_bounds__(256, 2)
joiner_gemm_kernel(const float* __restrict__ src, const float* __restrict__ tgt,
                   const float* __restrict__ bias, float* __restrict__ out)
{
    __shared__ __half As[2][TILE_H];
    __shared__ __half Bs[2][TILE_H];

    const int tid  = threadIdx.x;
    const int lane = tid & 31;
    const int warp = tid >> 5;
    const int warp_row = warp >> 2;
    const int warp_col = warp & 3;
    const int v0 = blockIdx.x * BN;
    const int m_base = blockIdx.y * BM;

    float acc[4][4][4];
    #pragma unroll
    for (int i = 0; i < 4; ++i)
        #pragma unroll
        for (int j = 0; j < 4; ++j)
            #pragma unroll
            for (int k = 0; k < 4; ++k) acc[i][j][k] = 0.f;

    // ---- prologue: chunk 0 ----
    cp_B(Bs[0], v0, 0, tid);
    CP_COMMIT();
    {
        float4 rs[4], rt[4];
        load_A(src, tgt, m_base, 0, tid, rs, rt);
        store_A(As[0], tid, rs, rt);
    }
    CP_WAIT0();
    __syncthreads();

    // ---- main pipeline: one sync per chunk ----
    for (int c = 0; c < NCHUNK; ++c) {
        const int s = c & 1;
        float4 rs[4], rt[4];
        if (c < NCHUNK - 1) {
            cp_B(Bs[s ^ 1], v0, c + 1, tid);
            CP_COMMIT();
            load_A(src, tgt, m_base, c + 1, tid, rs, rt);
        }
        compute_chunk(As[s], Bs[s], warp_row, warp_col, lane, acc);
        if (c < NCHUNK - 1) store_A(As[s ^ 1], tid, rs, rt);
        CP_WAIT0();
        __syncthreads();
    }

    // ---- epilogue: bias + fp32 store ----
    #pragma unroll
    for (int nt = 0; nt < 4; ++nt) {
        int col = v0 + warp_col * 32 + nt * 8 + ((lane & 3) << 1);
        float2 bv = *(const float2*)(bias + col);
        #pragma unroll
        for (int mt = 0; mt < 4; ++mt) {
            int row = m_base + warp_row * 64 + mt * 16 + (lane >> 2);
            float2 r0 = make_float2(acc[mt][nt][0] + bv.x, acc[mt][nt][1] + bv.y);
            float2 r1 = make_float2(acc[mt][nt][2] + bv.x, acc[mt][nt][3] + bv.y);
            *(float2*)(out + (size_t)row * V_ + col)       = r0;
            *(float2*)(out + (size_t)(row + 8) * V_ + col) = r1;
        }
    }
}

extern "C" void kernel_launch(void* const* d_in, const int* in_sizes, int n_in,
                              void* d_out, int out_size) {
    const float* src  = (const float*)d_in[0];
    const int*   slen = (const int*)  d_in[1];
    const float* tgt  = (const float*)d_in[2];
    const int*   tlen = (const int*)  d_in[3];
    const float* W    = (const float*)d_in[4];
    const float* bias = (const float*)d_in[5];
    float* out = (float*)d_out;

    convert_w_kernel<<<512, 256>>>(W);

    dim3 grid(V_ / BN, (B_ * T_ * U_) / BM);   // (8, 1024)
    joiner_gemm_kernel<<<grid, 256>>>(src, tgt, bias, out);

    const long long N_OUT = (long long)B_ * T_ * U_ * V_;
    if ((long long)out_size >= N_OUT + 2 * B_) {
        write_lengths_kernel<<<1, 32>>>(slen, tlen, out + N_OUT);
    }
}

// round 10
// speedup vs baseline: 1.5148x; 1.2503x over previous
#include <cuda_runtime.h>
#include <cuda_fp16.h>
#include <cstdint>

// Problem constants
#define B_  8
#define T_  256
#define U_  64
#define D_  512
#define V_  1024

// Tiling
#define BM 128            // rows per CTA tile
#define BN 128            // cols per CTA tile
#define KC 32             // k-chunk (2 x K=16 MMA steps)
#define NCHUNK 16         // D_/KC
#define ST 40             // smem row stride in halves (32 + 8 pad) -> 80B, conflict-free
#define TILE_H (BM * ST)  // 5120 halves per stage

// fp16 scratch for all GEMM operands (allocation-free per harness rules)
__device__ __align__(16) __half g_W16[V_ * D_];
__device__ __align__(16) __half g_S16[B_ * T_ * D_];   // 1,048,576
__device__ __align__(16) __half g_T16[B_ * U_ * D_];   // 262,144

__global__ void convert_f2h_kernel(const float* __restrict__ in, __half* __restrict__ out) {
    int i = (blockIdx.x * blockDim.x + threadIdx.x) * 4;
    float4 w = *(const float4*)(in + i);
    union { __half2 h[2]; uint2 u; } pack;
    pack.h[0] = __floats2half2_rn(w.x, w.y);
    pack.h[1] = __floats2half2_rn(w.z, w.w);
    *(uint2*)(out + i) = pack.u;
}

__global__ void write_lengths_kernel(const int* __restrict__ slen,
                                     const int* __restrict__ tlen,
                                     float* __restrict__ out_tail) {
    int i = threadIdx.x;
    if (i < B_)          out_tail[i] = (float)slen[i];
    else if (i < 2 * B_) out_tail[i] = (float)tlen[i - B_];
}

__device__ __forceinline__ void cp_async16(void* smem_dst, const void* gsrc) {
    uint32_t d = (uint32_t)__cvta_generic_to_shared(smem_dst);
    asm volatile("cp.async.ca.shared.global [%0], [%1], 16;" :: "r"(d), "l"(gsrc));
}
#define CP_COMMIT() asm volatile("cp.async.commit_group;" ::: "memory")
#define CP_WAIT0()  asm volatile("cp.async.wait_group 0;" ::: "memory")

// cp.async chunk c of B into stage buffer (64B per row = 4x16B; 2 ops/thread).
__device__ __forceinline__ void cp_B(__half* Bs_s, int v0, int c, int tid) {
    #pragma unroll
    for (int it = 0; it < 2; ++it) {
        int G = tid + it * 256;       // 0..511 : 16B group id
        int n = G >> 2;               // B row 0..127
        int g = G & 3;                // 16B group within row
        cp_async16(Bs_s + n * ST + g * 8,
                   g_W16 + (size_t)(v0 + n) * D_ + c * KC + g * 8);
    }
}

// Load chunk c's fp16 A operands (2 threads per row, 16 halves each stream).
__device__ __forceinline__ void load_A(int m_base, int c, int tid,
                                       uint4 rs[2], uint4 rt[2]) {
    int r = tid >> 1, h = tid & 1;
    int b = m_base >> 14;
    int t_idx = ((m_base & 16383) >> 6) + (r >> 6);
    const uint4* sp = (const uint4*)(g_S16 + (size_t)(b * T_ + t_idx) * D_ + c * KC + h * 16);
    const uint4* tp = (const uint4*)(g_T16 + (size_t)(b * U_ + (r & 63)) * D_ + c * KC + h * 16);
    rs[0] = sp[0]; rs[1] = sp[1];
    rt[0] = tp[0]; rt[1] = tp[1];
}

// relu(src+tgt) in half2, store 16 halves.
__device__ __forceinline__ void store_A(__half* __restrict__ As_s, int tid,
                                        const uint4 rs[2], const uint4 rt[2]) {
    int r = tid >> 1, h = tid & 1;
    __half* dst = As_s + r * ST + h * 16;
    const __half2 z = __float2half2_rn(0.f);
    #pragma unroll
    for (int j = 0; j < 2; ++j) {
        union { uint4 v; __half2 h2[4]; } a, b, o;
        a.v = rs[j]; b.v = rt[j];
        #pragma unroll
        for (int q = 0; q < 4; ++q) o.h2[q] = __hmax2(__hadd2(a.h2[q], b.h2[q]), z);
        *(uint4*)(dst + j * 8) = o.v;
    }
}

__device__ __forceinline__ void compute_chunk(const __half* __restrict__ As_s,
                                              const __half* __restrict__ Bs_s,
                                              int warp_row, int warp_col, int lane,
                                              float acc[4][4][4]) {
    #pragma unroll
    for (int kk = 0; kk < KC; kk += 16) {
        uint32_t afr[4][4], bfr[4][2];
        #pragma unroll
        for (int mt = 0; mt < 4; ++mt) {
            int row = warp_row * 64 + mt * 16 + (lane & 15);
            int col = kk + ((lane >> 4) << 3);
            uint32_t addr = (uint32_t)__cvta_generic_to_shared(As_s + row * ST + col);
            asm volatile("ldmatrix.sync.aligned.m8n8.x4.shared.b16 {%0,%1,%2,%3}, [%4];"
                         : "=r"(afr[mt][0]), "=r"(afr[mt][1]), "=r"(afr[mt][2]), "=r"(afr[mt][3])
                         : "r"(addr));
        }
        #pragma unroll
        for (int nt = 0; nt < 4; ++nt) {
            int row = warp_col * 32 + nt * 8 + (lane & 7);
            int col = kk + (((lane >> 3) & 1) << 3);
            uint32_t addr = (uint32_t)__cvta_generic_to_shared(Bs_s + row * ST + col);
            asm volatile("ldmatrix.sync.aligned.m8n8.x2.shared.b16 {%0,%1}, [%2];"
                         : "=r"(bfr[nt][0]), "=r"(bfr[nt][1])
                         : "r"(addr));
        }
        #pragma unroll
        for (int mt = 0; mt < 4; ++mt)
            #pragma unroll
            for (int nt = 0; nt < 4; ++nt) {
                asm volatile(
                    "mma.sync.aligned.m16n8k16.row.col.f32.f16.f16.f32 "
                    "{%0,%1,%2,%3}, {%4,%5,%6,%7}, {%8,%9}, {%0,%1,%2,%3};"
                    : "+f"(acc[mt][nt][0]), "+f"(acc[mt][nt][1]),
                      "+f"(acc[mt][nt][2]), "+f"(acc[mt][nt][3])
                    : "r"(afr[mt][0]), "r"(afr[mt][1]), "r"(afr[mt][2]), "r"(afr[mt][3]),
                      "r"(bfr[nt][0]), "r"(bfr[nt][1]));
            }
    }
}

__global__ void __launch_bounds__(256, 2)
joiner_gemm_kernel(const float* __restrict__ bias, float* __restrict__ out)
{
    __shared__ __half As[2][TILE_H];
    __shared__ __half Bs[2][TILE_H];

    const int tid  = threadIdx.x;
    const int lane = tid & 31;
    const int warp = tid >> 5;
    const int warp_row = warp >> 2;
    const int warp_col = warp & 3;
    const int v0 = blockIdx.x * BN;
    const int m_base = blockIdx.y * BM;

    float acc[4][4][4];
    #pragma unroll
    for (int i = 0; i < 4; ++i)
        #pragma unroll
        for (int j = 0; j < 4; ++j)
            #pragma unroll
            for (int k = 0; k < 4; ++k) acc[i][j][k] = 0.f;

    // ---- prologue: chunk 0 ----
    cp_B(Bs[0], v0, 0, tid);
    CP_COMMIT();
    {
        uint4 rs[2], rt[2];
        load_A(m_base, 0, tid, rs, rt);
        store_A(As[0], tid, rs, rt);
    }
    CP_WAIT0();
    __syncthreads();

    // ---- main pipeline: one sync per chunk ----
    for (int c = 0; c < NCHUNK; ++c) {
        const int s = c & 1;
        uint4 rs[2], rt[2];
        if (c < NCHUNK - 1) {
            cp_B(Bs[s ^ 1], v0, c + 1, tid);
            CP_COMMIT();
            load_A(m_base, c + 1, tid, rs, rt);
        }
        compute_chunk(As[s], Bs[s], warp_row, warp_col, lane, acc);
        if (c < NCHUNK - 1) store_A(As[s ^ 1], tid, rs, rt);
        CP_WAIT0();
        __syncthreads();
    }

    // ---- epilogue: bias + fp32 store ----
    #pragma unroll
    for (int nt = 0; nt < 4; ++nt) {
        int col = v0 + warp_col * 32 + nt * 8 + ((lane & 3) << 1);
        float2 bv = *(const float2*)(bias + col);
        #pragma unroll
        for (int mt = 0; mt < 4; ++mt) {
            int row = m_base + warp_row * 64 + mt * 16 + (lane >> 2);
            float2 r0 = make_float2(acc[mt][nt][0] + bv.x, acc[mt][nt][1] + bv.y);
            float2 r1 = make_float2(acc[mt][nt][2] + bv.x, acc[mt][nt][3] + bv.y);
            *(float2*)(out + (size_t)row * V_ + col)       = r0;
            *(float2*)(out + (size_t)(row + 8) * V_ + col) = r1;
        }
    }
}

extern "C" void kernel_launch(void* const* d_in, const int* in_sizes, int n_in,
                              void* d_out, int out_size) {
    const float* src  = (const float*)d_in[0];
    const int*   slen = (const int*)  d_in[1];
    const float* tgt  = (const float*)d_in[2];
    const int*   tlen = (const int*)  d_in[3];
    const float* W    = (const float*)d_in[4];
    const float* bias = (const float*)d_in[5];
    float* out = (float*)d_out;

    // fp16 conversions: W (524288), src (1048576), tgt (262144)
    {
        __half* w16; cudaGetSymbolAddress((void**)&w16, g_W16);
        __half* s16; cudaGetSymbolAddress((void**)&s16, g_S16);
        __half* t16; cudaGetSymbolAddress((void**)&t16, g_T16);
        convert_f2h_kernel<<<512, 256>>>(W, w16);
        convert_f2h_kernel<<<1024, 256>>>(src, s16);
        convert_f2h_kernel<<<256, 256>>>(tgt, t16);
    }

    dim3 grid(V_ / BN, (B_ * T_ * U_) / BM);   // (8, 1024)
    joiner_gemm_kernel<<<grid, 256>>>(bias, out);

    const long long N_OUT = (long long)B_ * T_ * U_ * V_;
    if ((long long)out_size >= N_OUT + 2 * B_) {
        write_lengths_kernel<<<1, 32>>>(slen, tlen, out + N_OUT);
    }
}